// round 11
// baseline (speedup 1.0000x reference)
#include <cuda_runtime.h>

#define BATCH 32
#define DIM   1024
#define INNER 2048
#define ZLEV  128              // colsum z-slices per batch (16 rows each)

// ---------------- device scratch ----------------
__device__ __align__(16) float g_qkvpart[16 * BATCH * 4096];     // [dc][b][j]
__device__ __align__(16) float g_colpart[4 * ZLEV * INNER];      // [parity*2+half][z][j]
__device__ __align__(16) float g_kp[BATCH * INNER];
__device__ __align__(16) float g_qp[BATCH * INNER];
__device__ __align__(16) float g_vv[BATCH * INNER];
__device__ __align__(16) float g_beta[BATCH];
__device__ __align__(16) float g_outv[BATCH * INNER];
__device__ __align__(16) float g_opart[64 * BATCH * DIM];        // [ic][b][jo]

// ---------------- K1: qkv partial GEMM (256 blocks) ------------------
__global__ __launch_bounds__(256) void k_qkv(const float* __restrict__ x,
                                             const float* __restrict__ Wq,
                                             const float* __restrict__ Wk,
                                             const float* __restrict__ Wv) {
    __shared__ __align__(16) float shx[32 * 64];
    const int jc = blockIdx.x & 15, dc = blockIdx.x >> 4, tid = threadIdx.x;
    for (int t = tid; t < 32 * 64; t += 256) {
        int b = t >> 6, dd = t & 63;
        shx[t] = x[b * DIM + dc * 64 + dd];
    }
    __syncthreads();

    const int j = jc * 256 + tid;  // 0..4095
    const float* Wm; int col, ncols;
    if (j < 1024)      { Wm = Wq; col = j;        ncols = 1024; }
    else if (j < 2048) { Wm = Wk; col = j - 1024; ncols = 1024; }
    else               { Wm = Wv; col = j - 2048; ncols = 2048; }

    float acc[32];
#pragma unroll
    for (int b = 0; b < 32; b++) acc[b] = 0.f;
    const float* wp = Wm + (size_t)(dc * 64) * ncols + col;
    for (int dd = 0; dd < 64; dd += 4) {
        float w0 = wp[(size_t)(dd + 0) * ncols];
        float w1 = wp[(size_t)(dd + 1) * ncols];
        float w2 = wp[(size_t)(dd + 2) * ncols];
        float w3 = wp[(size_t)(dd + 3) * ncols];
#pragma unroll
        for (int b = 0; b < 32; b++) {
            const float4 xv = *(const float4*)&shx[b * 64 + dd];
            acc[b] = fmaf(xv.x, w0, fmaf(xv.y, w1, fmaf(xv.z, w2, fmaf(xv.w, w3, acc[b]))));
        }
    }
#pragma unroll
    for (int b = 0; b < 32; b++)
        g_qkvpart[(size_t)(dc * 32 + b) * 4096 + j] = acc[b];
}

// ---------------- K2: mid = beta, kp, qp, vv -------------------------
__device__ __forceinline__ float sum16_qkv(int b, int j) {
    float s = 0.f;
#pragma unroll
    for (int dc = 0; dc < 16; dc++) s += g_qkvpart[(size_t)(dc * 32 + b) * 4096 + j];
    return s;
}
__device__ __forceinline__ float feat(int b, int j, int base, const float* __restrict__ bias) {
    const int c = j & 1023;
    float v = sum16_qkv(b, base + c) + bias[c];
    v = (j < 1024) ? v : -v;
    return fmaxf(v, 0.f);
}
__global__ __launch_bounds__(256) void k_mid(const float* __restrict__ x,
                                             const float* __restrict__ Wb,
                                             const float* __restrict__ bb,
                                             const float* __restrict__ bq,
                                             const float* __restrict__ bk,
                                             const float* __restrict__ bv) {
    const int jc = blockIdx.x, b = blockIdx.y, tid = threadIdx.x;
    float s = 0.f;
    for (int d = tid; d < DIM; d += 256) s += x[b * DIM + d] * Wb[d];
#pragma unroll
    for (int o = 16; o; o >>= 1) s += __shfl_down_sync(0xffffffffu, s, o);
    __shared__ float shr[8];
    if ((tid & 31) == 0) shr[tid >> 5] = s;
    __syncthreads();
    if (tid == 0 && jc == 0) {
        float t = 0.f;
#pragma unroll
        for (int u = 0; u < 8; u++) t += shr[u];
        t += bb[0];
        g_beta[b] = 1.f / (1.f + expf(-t));
    }
    const int j = jc * 256 + tid;
    const int jm = (j + INNER - 1) & (INNER - 1);
    g_kp[b * INNER + j] = feat(b, j, 1024, bk) * feat(b, jm, 1024, bk);
    g_qp[b * INNER + j] = feat(b, j, 0, bq) * feat(b, jm, 0, bq);
    g_vv[b * INNER + j] = sum16_qkv(b, 2048 + j) + bv[j];
}

// ---------------- K3: pipe = update(gu) [512 blk] || colsum(gc) [256 blk]
// Lag-1: colsum(g) in launch g leaves W_g resident in L2; update(g) in
// launch g+1 re-reads it from L2 while colsum(g+1) streams from DRAM.
// Both roles move 128 KB per block -> balanced durations, full overlap.
__global__ __launch_bounds__(256) void k_pipe(const float* __restrict__ W,
                                              float* __restrict__ wnew,
                                              int gc, int gu) {
    const int bid = blockIdx.x, tid = threadIdx.x;

    if (bid < 512) {
        // ---------------- update role ----------------
        if (gu < 0) return;
        const int half = bid >> 8;               // batch within group
        const int batch = gu * 2 + half;
        const int i0 = (bid & 255) * 8;
        __shared__ __align__(16) float smem[INNER];
        for (int t = tid; t < INNER; t += 256) smem[t] = g_kp[batch * INNER + t];
        __syncthreads();

        const int w = tid >> 5, lane = tid & 31;
        const int i = i0 + w;                    // exactly one row per warp

        // column-sum over ZLEV partials for this row index
        const float* cpb = g_colpart + (size_t)(((gu & 1) * 2 + half) * ZLEV) * INNER;
        float cs = 0.f;
#pragma unroll
        for (int z = lane; z < ZLEV; z += 32) cs += cpb[(size_t)z * INNER + i];
#pragma unroll
        for (int o = 16; o; o >>= 1) cs += __shfl_xor_sync(0xffffffffu, cs, o);
        const float dvi = g_beta[batch] * (g_vv[batch * INNER + i] - cs * smem[i]);

        const size_t base = ((size_t)batch * INNER + i) * INNER;
        const float4* Wr = (const float4*)(W + base);
        float4* Or = (float4*)(wnew + base);
        const float4* kp4 = (const float4*)smem;
        float lsum = 0.f;
#pragma unroll 4
        for (int t = lane; t < 512; t += 32) {
            float4 wv = __ldcg(&Wr[t]);          // L2 hit (resident from prev launch)
            float4 k4 = kp4[t];
            float4 r;
            r.x = fmaf(dvi, k4.x, wv.x);
            r.y = fmaf(dvi, k4.y, wv.y);
            r.z = fmaf(dvi, k4.z, wv.z);
            r.w = fmaf(dvi, k4.w, wv.w);
            __stcs(&Or[t], r);                   // evict-first: protect resident W
            lsum += (r.x + r.y) + (r.z + r.w);
        }
#pragma unroll
        for (int o = 16; o; o >>= 1) lsum += __shfl_down_sync(0xffffffffu, lsum, o);
        if (lane == 0) g_outv[batch * INNER + i] = lsum * g_qp[batch * INNER + i];
    } else {
        // ---------------- colsum role (float4 streaming) ----------------
        if (gc < 0) return;
        const int cb = bid - 512;                // 0..255
        const int half = cb >> 7;                // batch within group
        const int batch = gc * 2 + half;
        const int z = cb & 127;                  // 16 rows per z-slice
        const size_t rowbase = ((size_t)batch * INNER + z * 16) * INNER;
        float* cpb = g_colpart + (size_t)(((gc & 1) * 2 + half) * ZLEV + z) * INNER;
#pragma unroll
        for (int h = 0; h < 2; h++) {
            const int c = h * 1024 + tid * 4;
            const float4* p = (const float4*)(W + rowbase + c);
            float4 a0 = {0,0,0,0}, a1 = {0,0,0,0}, a2 = {0,0,0,0}, a3 = {0,0,0,0};
#pragma unroll
            for (int r = 0; r < 16; r += 4) {
                float4 v0 = __ldcg(&p[(size_t)(r + 0) * 512]);
                float4 v1 = __ldcg(&p[(size_t)(r + 1) * 512]);
                float4 v2 = __ldcg(&p[(size_t)(r + 2) * 512]);
                float4 v3 = __ldcg(&p[(size_t)(r + 3) * 512]);
                a0.x += v0.x; a0.y += v0.y; a0.z += v0.z; a0.w += v0.w;
                a1.x += v1.x; a1.y += v1.y; a1.z += v1.z; a1.w += v1.w;
                a2.x += v2.x; a2.y += v2.y; a2.z += v2.z; a2.w += v2.w;
                a3.x += v3.x; a3.y += v3.y; a3.z += v3.z; a3.w += v3.w;
            }
            float4 s;
            s.x = (a0.x + a1.x) + (a2.x + a3.x);
            s.y = (a0.y + a1.y) + (a2.y + a3.y);
            s.z = (a0.z + a1.z) + (a2.z + a3.z);
            s.w = (a0.w + a1.w) + (a2.w + a3.w);
            *(float4*)(cpb + c) = s;
        }
    }
}

// ---------------- K4: out partials = outv @ Wo (256 CTAs) ------------
__global__ __launch_bounds__(256) void k_outpart(const float* __restrict__ Wo) {
    __shared__ __align__(16) float sh[32 * 32];
    const int jc = blockIdx.x, ic = blockIdx.y, tid = threadIdx.x;
    for (int t = tid; t < 32 * 32; t += 256) {
        int b = t >> 5, ii = t & 31;
        sh[t] = g_outv[b * INNER + ic * 32 + ii];
    }
    __syncthreads();

    const int jo = jc * 256 + tid;
    float acc[32];
#pragma unroll
    for (int b = 0; b < 32; b++) acc[b] = 0.f;
    const float* wp = Wo + (size_t)(ic * 32) * DIM + jo;
#pragma unroll
    for (int ii = 0; ii < 32; ii += 4) {
        float w0 = wp[(size_t)(ii + 0) * DIM];
        float w1 = wp[(size_t)(ii + 1) * DIM];
        float w2 = wp[(size_t)(ii + 2) * DIM];
        float w3 = wp[(size_t)(ii + 3) * DIM];
#pragma unroll
        for (int b = 0; b < 32; b++) {
            const float4 xv = *(const float4*)&sh[b * 32 + ii];
            acc[b] = fmaf(xv.x, w0, fmaf(xv.y, w1, fmaf(xv.z, w2, fmaf(xv.w, w3, acc[b]))));
        }
    }
#pragma unroll
    for (int b = 0; b < 32; b++)
        g_opart[(size_t)(ic * 32 + b) * DIM + jo] = acc[b];
}

// ---------------- K5: out finalize -----------------------------------
__global__ __launch_bounds__(256) void k_outfinal(const float* __restrict__ bo,
                                                  float* __restrict__ out) {
    const int idx = blockIdx.x * 256 + threadIdx.x;  // 32768
    const int jo = idx & 1023, b = idx >> 10;
    float s = bo[jo];
#pragma unroll
    for (int ic = 0; ic < 64; ic++) s += g_opart[(size_t)(ic * 32 + b) * DIM + jo];
    out[idx] = s;
}

// ---------------- launch ---------------------------------------------
extern "C" void kernel_launch(void* const* d_in, const int* in_sizes, int n_in,
                              void* d_out, int out_size) {
    const float* x  = (const float*)d_in[0];
    const float* W  = (const float*)d_in[1];
    const float* Wq = (const float*)d_in[2];
    const float* bq = (const float*)d_in[3];
    const float* Wk = (const float*)d_in[4];
    const float* bk = (const float*)d_in[5];
    const float* Wv = (const float*)d_in[6];
    const float* bv = (const float*)d_in[7];
    const float* Wo = (const float*)d_in[8];
    const float* bo = (const float*)d_in[9];
    const float* Wb = (const float*)d_in[10];
    const float* bb = (const float*)d_in[11];

    float* out  = (float*)d_out;
    float* wnew = out + BATCH * DIM;

    k_qkv<<<256, 256>>>(x, Wq, Wk, Wv);
    k_mid<<<dim3(8, 32), 256>>>(x, Wb, bb, bq, bk, bv);
    // Lag-1 pipeline over 16 groups of 2 batches.
    for (int g = 0; g <= 16; g++) {
        const int gc = (g < 16) ? g : -1;
        const int gu = g - 1;
        k_pipe<<<768, 256>>>(W, wnew, gc, gu);
    }
    k_outpart <<<dim3(4, 64), 256>>>(Wo);
    k_outfinal<<<128,         256>>>(bo, out);
}

// round 13
// speedup vs baseline: 1.6113x; 1.6113x over previous
#include <cuda_runtime.h>

#define BATCH 32
#define DIM   1024
#define INNER 2048

// ---------------- device scratch ----------------
__device__ __align__(16) float g_qkvpart[8 * BATCH * 4096];    // [dc][b][j]
__device__ __align__(16) float g_colpart[16 * BATCH * INNER];  // [z][b][j]
__device__ __align__(16) float g_kp[BATCH * INNER];
__device__ __align__(16) float g_qp[BATCH * INNER];
__device__ __align__(16) float g_dv[BATCH * INNER];
__device__ __align__(16) float g_outv[BATCH * INNER];
__device__ __align__(16) float g_opart[64 * BATCH * DIM];      // [ic][b][jo]

// ---------------- K1: fused colsum(W) + qkv partial GEMM -------------
// blocks [0, 1024): colsum of W, float4 streaming loads.
// blocks [1024, 1152): qkv partial GEMM (16 jchunks x 8 dchunks).
__global__ __launch_bounds__(256) void k_pass1(const float* __restrict__ x,
                                               const float* __restrict__ Wq,
                                               const float* __restrict__ Wk,
                                               const float* __restrict__ Wv,
                                               const float* __restrict__ W) {
    __shared__ __align__(16) float shx[32 * 128];
    const int bid = blockIdx.x, tid = threadIdx.x;

    if (bid < 1024) {
        // ---- colsum branch: block = (jc, b, z); 128 rows x 1024 cols ----
        const int jc = bid & 1, b = (bid >> 1) & 31, z = bid >> 6;
        const int c = jc * 1024 + tid * 4;
        const float4* p = (const float4*)(W + ((size_t)(b * INNER + z * 128)) * INNER + c);
        float4 a0 = {0,0,0,0}, a1 = {0,0,0,0}, a2 = {0,0,0,0}, a3 = {0,0,0,0};
        for (int r = 0; r < 128; r += 4) {
            float4 v0 = __ldcs(&p[(size_t)(r + 0) * 512]);
            float4 v1 = __ldcs(&p[(size_t)(r + 1) * 512]);
            float4 v2 = __ldcs(&p[(size_t)(r + 2) * 512]);
            float4 v3 = __ldcs(&p[(size_t)(r + 3) * 512]);
            a0.x += v0.x; a0.y += v0.y; a0.z += v0.z; a0.w += v0.w;
            a1.x += v1.x; a1.y += v1.y; a1.z += v1.z; a1.w += v1.w;
            a2.x += v2.x; a2.y += v2.y; a2.z += v2.z; a2.w += v2.w;
            a3.x += v3.x; a3.y += v3.y; a3.z += v3.z; a3.w += v3.w;
        }
        float4 s;
        s.x = (a0.x + a1.x) + (a2.x + a3.x);
        s.y = (a0.y + a1.y) + (a2.y + a3.y);
        s.z = (a0.z + a1.z) + (a2.z + a3.z);
        s.w = (a0.w + a1.w) + (a2.w + a3.w);
        *(float4*)(g_colpart + ((size_t)(z * 32 + b)) * INNER + c) = s;
    } else {
        // ---- qkv partial GEMM branch ----
        const int qid = bid - 1024;
        const int jc = qid & 15, dc = qid >> 4;
        for (int t = tid; t < 32 * 128; t += 256) {
            int b = t >> 7, dd = t & 127;
            shx[t] = x[b * DIM + dc * 128 + dd];
        }
        __syncthreads();

        const int j = jc * 256 + tid;  // 0..4095
        const float* Wm; int col, ncols;
        if (j < 1024)      { Wm = Wq; col = j;        ncols = 1024; }
        else if (j < 2048) { Wm = Wk; col = j - 1024; ncols = 1024; }
        else               { Wm = Wv; col = j - 2048; ncols = 2048; }

        float acc[32];
#pragma unroll
        for (int b = 0; b < 32; b++) acc[b] = 0.f;
        const float* wp = Wm + (size_t)(dc * 128) * ncols + col;
        for (int dd = 0; dd < 128; dd += 4) {
            float w0 = wp[(size_t)(dd + 0) * ncols];
            float w1 = wp[(size_t)(dd + 1) * ncols];
            float w2 = wp[(size_t)(dd + 2) * ncols];
            float w3 = wp[(size_t)(dd + 3) * ncols];
#pragma unroll
            for (int b = 0; b < 32; b++) {
                const float4 xv = *(const float4*)&shx[b * 128 + dd];
                acc[b] = fmaf(xv.x, w0, fmaf(xv.y, w1, fmaf(xv.z, w2, fmaf(xv.w, w3, acc[b]))));
            }
        }
#pragma unroll
        for (int b = 0; b < 32; b++)
            g_qkvpart[(size_t)(dc * 32 + b) * 4096 + j] = acc[b];
    }
}

// ---------------- K2: beta, kp, qp, dv (from L2-hot partials) --------
__device__ __forceinline__ float sum8_qkv(int b, int j) {
    float s = 0.f;
#pragma unroll
    for (int dc = 0; dc < 8; dc++) s += g_qkvpart[(size_t)(dc * 32 + b) * 4096 + j];
    return s;
}

__device__ __forceinline__ float feat(int b, int j, int base, const float* __restrict__ bias) {
    const int c = j & 1023;
    float v = sum8_qkv(b, base + c) + bias[c];
    v = (j < 1024) ? v : -v;
    return fmaxf(v, 0.f);
}

__global__ __launch_bounds__(256) void k_mid(const float* __restrict__ x,
                                             const float* __restrict__ Wb,
                                             const float* __restrict__ bb,
                                             const float* __restrict__ bq,
                                             const float* __restrict__ bk,
                                             const float* __restrict__ bv) {
    const int b = blockIdx.y, jc = blockIdx.x, tid = threadIdx.x;

    // beta = sigmoid(x[b] . Wb + bb)
    float s = 0.f;
    for (int d = tid; d < DIM; d += 256) s += x[b * DIM + d] * Wb[d];
#pragma unroll
    for (int o = 16; o; o >>= 1) s += __shfl_down_sync(0xffffffffu, s, o);
    __shared__ float shr[8];
    __shared__ float sbeta;
    if ((tid & 31) == 0) shr[tid >> 5] = s;
    __syncthreads();
    if (tid == 0) {
        float t = 0.f;
#pragma unroll
        for (int u = 0; u < 8; u++) t += shr[u];
        t += bb[0];
        sbeta = 1.f / (1.f + expf(-t));
    }
    __syncthreads();
    const float beta = sbeta;

    const int j = jc * 256 + tid;
    const int jm = (j + INNER - 1) & (INNER - 1);

    const float kpv = feat(b, j, 1024, bk) * feat(b, jm, 1024, bk);
    g_kp[b * INNER + j] = kpv;
    g_qp[b * INNER + j] = feat(b, j, 0, bq) * feat(b, jm, 0, bq);

    const float vv = sum8_qkv(b, 2048 + j) + bv[j];
    float cs = 0.f;
#pragma unroll
    for (int z = 0; z < 16; z++) cs += g_colpart[(size_t)(z * 32 + b) * INNER + j];
    g_dv[b * INNER + j] = beta * (vv - cs * kpv);
}

// ---------------- K3: W_new = W + dv⊗kp, fused row-sum --------------
// grid (256 rowgroups of 8, 32 b), 256 threads = 8 warps, one warp per row.
__global__ __launch_bounds__(256) void k_update(const float* __restrict__ W,
                                                float* __restrict__ wnew) {
    const int b = blockIdx.y, tid = threadIdx.x;
    const int i0 = blockIdx.x * 8;
    __shared__ __align__(16) float4 shkp[512];
    const float4* kpv4 = (const float4*)(g_kp + b * INNER);
    for (int t = tid; t < 512; t += 256) shkp[t] = kpv4[t];
    __syncthreads();

    const int w = tid >> 5, lane = tid & 31;
    const int i = i0 + w;
    const size_t base = ((size_t)b * INNER + i) * INNER;
    const float4* Wr = (const float4*)(W + base);
    float4* Or = (float4*)(wnew + base);
    const float dvi = g_dv[b * INNER + i];

    float lsum = 0.f;
#pragma unroll
    for (int t = lane; t < 512; t += 32) {
        float4 wv = __ldcs(&Wr[t]);
        float4 kp4 = shkp[t];
        float4 r;
        r.x = fmaf(dvi, kp4.x, wv.x);
        r.y = fmaf(dvi, kp4.y, wv.y);
        r.z = fmaf(dvi, kp4.z, wv.z);
        r.w = fmaf(dvi, kp4.w, wv.w);
        __stcs(&Or[t], r);
        lsum += (r.x + r.y) + (r.z + r.w);
    }
#pragma unroll
    for (int o = 16; o; o >>= 1) lsum += __shfl_down_sync(0xffffffffu, lsum, o);
    if (lane == 0) g_outv[b * INNER + i] = lsum * g_qp[b * INNER + i];
}

// ---------------- K4: out partials = outv @ Wo (256 CTAs) ------------
__global__ __launch_bounds__(256) void k_outpart(const float* __restrict__ Wo) {
    __shared__ __align__(16) float sh[32 * 32];
    const int jc = blockIdx.x, ic = blockIdx.y, tid = threadIdx.x;
    for (int t = tid; t < 32 * 32; t += 256) {
        int b = t >> 5, ii = t & 31;
        sh[t] = g_outv[b * INNER + ic * 32 + ii];
    }
    __syncthreads();

    const int jo = jc * 256 + tid;
    float acc[32];
#pragma unroll
    for (int b = 0; b < 32; b++) acc[b] = 0.f;
    const float* wp = Wo + (size_t)(ic * 32) * DIM + jo;
#pragma unroll
    for (int ii = 0; ii < 32; ii += 4) {
        float w0 = wp[(size_t)(ii + 0) * DIM];
        float w1 = wp[(size_t)(ii + 1) * DIM];
        float w2 = wp[(size_t)(ii + 2) * DIM];
        float w3 = wp[(size_t)(ii + 3) * DIM];
#pragma unroll
        for (int b = 0; b < 32; b++) {
            const float4 xv = *(const float4*)&sh[b * 32 + ii];
            acc[b] = fmaf(xv.x, w0, fmaf(xv.y, w1, fmaf(xv.z, w2, fmaf(xv.w, w3, acc[b]))));
        }
    }
#pragma unroll
    for (int b = 0; b < 32; b++)
        g_opart[(size_t)(ic * 32 + b) * DIM + jo] = acc[b];
}

// ---------------- K5: out finalize -----------------------------------
__global__ __launch_bounds__(256) void k_outfinal(const float* __restrict__ bo,
                                                  float* __restrict__ out) {
    const int idx = blockIdx.x * 256 + threadIdx.x;  // 32768
    const int jo = idx & 1023, b = idx >> 10;
    float s = bo[jo];
#pragma unroll
    for (int ic = 0; ic < 64; ic++) s += g_opart[(size_t)(ic * 32 + b) * DIM + jo];
    out[idx] = s;
}

// ---------------- launch ---------------------------------------------
extern "C" void kernel_launch(void* const* d_in, const int* in_sizes, int n_in,
                              void* d_out, int out_size) {
    const float* x  = (const float*)d_in[0];
    const float* W  = (const float*)d_in[1];
    const float* Wq = (const float*)d_in[2];
    const float* bq = (const float*)d_in[3];
    const float* Wk = (const float*)d_in[4];
    const float* bk = (const float*)d_in[5];
    const float* Wv = (const float*)d_in[6];
    const float* bv = (const float*)d_in[7];
    const float* Wo = (const float*)d_in[8];
    const float* bo = (const float*)d_in[9];
    const float* Wb = (const float*)d_in[10];
    const float* bb = (const float*)d_in[11];

    float* out  = (float*)d_out;
    float* wnew = out + BATCH * DIM;

    k_pass1   <<<1152,          256>>>(x, Wq, Wk, Wv, W);
    k_mid     <<<dim3(8, 32),   256>>>(x, Wb, bb, bq, bk, bv);
    k_update  <<<dim3(256, 32), 256>>>(W, wnew);
    k_outpart <<<dim3(4, 64),   256>>>(Wo);
    k_outfinal<<<128,           256>>>(bo, out);
}